// round 7
// baseline (speedup 1.0000x reference)
#include <cuda_runtime.h>

// ---------------------------------------------------------------------------
// bPC SNN: 25 steps of predictive-coding spiking network dynamics.
// Layers [1024, 4096, 4096, 4096, 512], batch 512, fp32.
//
// Round-5 strategy:
//   - Pipelined fp32 SIMT GEMM: 128x128 tile, BK=16, 256 thr, 8x8/thread,
//     double-buffered smem + register-staged global prefetch + double-buffered
//     fragments. __launch_bounds__(256,1): grid (~128) < #SM (148) means
//     1 CTA/SM regardless, so spend registers on pipelining, not occupancy.
//   - Two-segment K loop: phase-A pairs  t_i = [eg_{i-1}|ed_{i+1}] @ [W;V]
//     merged into single launches (K = 5120 / 8192 / 4608).
//   - Split-K (4x / 8x) for the small-N GEMMs eg0 (N=1024) and ed4 (N=512)
//     into __device__ partial slabs + tiny reduce kernel -> 128 CTAs each.
//   - Error tensors live directly inside d_out (row stride 26112) -> the
//     final concat is free; next-step GEMMs read d_out slices as A operands.
//   - x_data@V0^T and y@W3^T are step-invariant -> precomputed; ed1/eg3 fold
//     into the elementwise LIF kernel.
// ---------------------------------------------------------------------------

#define S_LAYER (512 * 4096)
#define OUT_LD  26112          // 1024 + 3*4096 + 3*4096 + 512

__device__ float g_state[9 * S_LAYER];      // j1,j2,j3 | v1,v2,v3 | x1,x2,x3
__device__ float g_tin[3 * S_LAYER];        // injected currents, layers 1..3
__device__ float g_c1h[S_LAYER];            // 0.5 * x_data @ V0^T
__device__ float g_c2h[S_LAYER];            // 0.5 * y_target @ W3^T
__device__ float g_pA[4 * 512 * 1024];      // eg0 split-K partials
__device__ float g_pB[8 * 512 * 512];       // ed4 split-K partials

constexpr int BM = 128, BN = 128, BK = 16, PAD = 4;

// ---------------------------------------------------------------------------
// GEMM: C = alpha * ( A1 @ op(B1) [K1]  +  A2 @ op(B2) [K2] ) + g0*aux0 + g1*aux1
//   TB=false: op(B) = B,  B is (K,N) row-major
//   TB=true : op(B) = B^T, B is (N,K) row-major
// If kc != 0: split-K mode (single segment), blockIdx.z selects K chunk of
// length kc; C is offset by z*czstride. M,N multiples of 128; K mult of 16.
// ---------------------------------------------------------------------------

struct GemmP {
    const float* A1; int lda1;
    const float* B1; int ldb1;
    const float* A2; int lda2;
    const float* B2; int ldb2;
    int K1, K2;
    float*       C; int ldc;
    const float* aux0; int ld0; float g0;
    const float* aux1; int ld1; float g1;
    float alpha;
    int  kc;
    long czstride;
};

template <bool TB>
__global__ __launch_bounds__(256, 1) void gemm_k(GemmP p) {
    __shared__ float As[2][BK][BM + PAD];
    __shared__ float Bs[2][BK][BN + PAD];

    const int tid  = threadIdx.x;
    const int bm   = blockIdx.y * BM;
    const int bn   = blockIdx.x * BN;
    const int ty   = tid >> 4;          // 0..15
    const int tx   = tid & 15;          // 0..15
    const int arow = tid >> 2;          // 0..63
    const int acol = (tid & 3) << 2;    // 0,4,8,12
    const int brow = tid >> 5;          // 0..7
    const int bcol = (tid & 31) << 2;   // 0..124

    const float* A1 = p.A1;
    const float* B1 = p.B1;
    int    K1 = p.K1;
    float* C  = p.C;
    if (p.kc) {                         // split-K
        A1 += (long)blockIdx.z * p.kc;
        B1 += (long)blockIdx.z * p.kc;  // TB only: k-offset along B rows
        K1  = p.kc;
        C  += (long)blockIdx.z * p.czstride;
    }
    const int nk = (K1 + p.K2) / BK;

    float acc[8][8];
#pragma unroll
    for (int i = 0; i < 8; i++)
#pragma unroll
        for (int j = 0; j < 8; j++) acc[i][j] = 0.0f;

    float4 ra0, ra1, rb0, rb1;

#define LOADG(kt_) do {                                                        \
    const int k0_ = (kt_) * BK;                                                \
    const float* Ap_; int lda_; const float* Bp_; int ldb_; int ka_;           \
    if (k0_ < K1) { Ap_ = A1; lda_ = p.lda1; Bp_ = B1;  ldb_ = p.ldb1; ka_ = k0_; } \
    else { Ap_ = p.A2; lda_ = p.lda2; Bp_ = p.B2; ldb_ = p.ldb2; ka_ = k0_ - K1; }  \
    ra0 = *(const float4*)(Ap_ + (long)(bm + arow)      * lda_ + ka_ + acol);  \
    ra1 = *(const float4*)(Ap_ + (long)(bm + arow + 64) * lda_ + ka_ + acol);  \
    if (TB) {                                                                  \
        rb0 = *(const float4*)(Bp_ + (long)(bn + arow)      * ldb_ + ka_ + acol); \
        rb1 = *(const float4*)(Bp_ + (long)(bn + arow + 64) * ldb_ + ka_ + acol); \
    } else {                                                                   \
        rb0 = *(const float4*)(Bp_ + (long)(ka_ + brow)     * ldb_ + bn + bcol);  \
        rb1 = *(const float4*)(Bp_ + (long)(ka_ + brow + 8) * ldb_ + bn + bcol);  \
    }                                                                          \
} while (0)

#define STORES(buf_) do {                                                      \
    As[buf_][acol + 0][arow]      = ra0.x;                                     \
    As[buf_][acol + 1][arow]      = ra0.y;                                     \
    As[buf_][acol + 2][arow]      = ra0.z;                                     \
    As[buf_][acol + 3][arow]      = ra0.w;                                     \
    As[buf_][acol + 0][arow + 64] = ra1.x;                                     \
    As[buf_][acol + 1][arow + 64] = ra1.y;                                     \
    As[buf_][acol + 2][arow + 64] = ra1.z;                                     \
    As[buf_][acol + 3][arow + 64] = ra1.w;                                     \
    if (TB) {                                                                  \
        Bs[buf_][acol + 0][arow]      = rb0.x;                                 \
        Bs[buf_][acol + 1][arow]      = rb0.y;                                 \
        Bs[buf_][acol + 2][arow]      = rb0.z;                                 \
        Bs[buf_][acol + 3][arow]      = rb0.w;                                 \
        Bs[buf_][acol + 0][arow + 64] = rb1.x;                                 \
        Bs[buf_][acol + 1][arow + 64] = rb1.y;                                 \
        Bs[buf_][acol + 2][arow + 64] = rb1.z;                                 \
        Bs[buf_][acol + 3][arow + 64] = rb1.w;                                 \
    } else {                                                                   \
        *(float4*)&Bs[buf_][brow][bcol]     = rb0;                             \
        *(float4*)&Bs[buf_][brow + 8][bcol] = rb1;                             \
    }                                                                          \
} while (0)

    float af[2][8], bf[2][8];
#define LDFRAG(d_, buf_, kk_) do {                                             \
    *(float4*)&af[d_][0] = *(const float4*)&As[buf_][kk_][ty * 8];             \
    *(float4*)&af[d_][4] = *(const float4*)&As[buf_][kk_][ty * 8 + 4];         \
    *(float4*)&bf[d_][0] = *(const float4*)&Bs[buf_][kk_][tx * 8];             \
    *(float4*)&bf[d_][4] = *(const float4*)&Bs[buf_][kk_][tx * 8 + 4];         \
} while (0)

    LOADG(0);
    STORES(0);
    __syncthreads();

    for (int kt = 0; kt < nk; ++kt) {
        const int cur = kt & 1;
        if (kt + 1 < nk) LOADG(kt + 1);      // global prefetch (in regs)
        LDFRAG(0, cur, 0);
#pragma unroll
        for (int kk = 0; kk < BK; ++kk) {
            const int c = kk & 1;
            if (kk + 1 < BK) LDFRAG(c ^ 1, cur, kk + 1);
#pragma unroll
            for (int i = 0; i < 8; ++i)
#pragma unroll
                for (int j = 0; j < 8; ++j)
                    acc[i][j] += af[c][i] * bf[c][j];
        }
        if (kt + 1 < nk) STORES(cur ^ 1);
        __syncthreads();
    }

    // ---- epilogue ----
#pragma unroll
    for (int i = 0; i < 8; ++i) {
        const long row = bm + ty * 8 + i;
        const int  col = bn + tx * 8;
        float r[8];
#pragma unroll
        for (int j = 0; j < 8; ++j) r[j] = p.alpha * acc[i][j];
        if (p.aux0) {
            const float* a0 = p.aux0 + row * p.ld0 + col;
            const float4 u0 = *(const float4*)(a0);
            const float4 u1 = *(const float4*)(a0 + 4);
            r[0] += p.g0 * u0.x; r[1] += p.g0 * u0.y;
            r[2] += p.g0 * u0.z; r[3] += p.g0 * u0.w;
            r[4] += p.g0 * u1.x; r[5] += p.g0 * u1.y;
            r[6] += p.g0 * u1.z; r[7] += p.g0 * u1.w;
        }
        if (p.aux1) {
            const float* a1 = p.aux1 + row * p.ld1 + col;
            const float4 u0 = *(const float4*)(a1);
            const float4 u1 = *(const float4*)(a1 + 4);
            r[0] += p.g1 * u0.x; r[1] += p.g1 * u0.y;
            r[2] += p.g1 * u0.z; r[3] += p.g1 * u0.w;
            r[4] += p.g1 * u1.x; r[5] += p.g1 * u1.y;
            r[6] += p.g1 * u1.z; r[7] += p.g1 * u1.w;
        }
        *(float4*)(C + row * p.ldc + col)     = make_float4(r[0], r[1], r[2], r[3]);
        *(float4*)(C + row * p.ldc + col + 4) = make_float4(r[4], r[5], r[6], r[7]);
    }
#undef LOADG
#undef STORES
#undef LDFRAG
}

// ---------------------------------------------------------------------------
// Split-K reduce: out[b, outoff+f] = 0.5*ref[b,f] - 0.5 * sum_z P[z][b,f]
// ---------------------------------------------------------------------------
__global__ void reduce_k(const float* __restrict__ P, int nsplit,
                         const float* __restrict__ ref, int ldref,
                         float* __restrict__ out, int outoff, int N) {
    const int idx = blockIdx.x * blockDim.x + threadIdx.x;
    if (idx >= 512 * N) return;
    const int  b    = idx / N;
    const int  f    = idx - b * N;
    const long slab = (long)512 * N;
    float s = 0.0f;
    for (int z = 0; z < nsplit; ++z) s += P[z * slab + idx];
    out[(long)b * OUT_LD + outoff + f] = 0.5f * ref[(long)b * ldref + f] - 0.5f * s;
}

// ---------------------------------------------------------------------------
// LIF elementwise update for layers 1..3; also emits ed1 and eg3.
// ---------------------------------------------------------------------------
__global__ void lif_k(float* dout) {
    const long idx = (long)blockIdx.x * blockDim.x + threadIdx.x;
    if (idx >= 3L * S_LAYER) return;
    const int L = (int)(idx / S_LAYER);          // 0..2 -> layers 1..3
    const int r = (int)(idx - (long)L * S_LAYER);

    const float tin = g_tin[idx];
    float j = g_state[idx];
    float v = g_state[3L * S_LAYER + idx];
    float x = g_state[6L * S_LAYER + idx];

    j = j + 0.25f * (tin - j);                    // dt/tau_j = 0.25
    v = v + 0.05f * (j - v);                      // dt/tau_m = 0.05
    const float spk = (v > 1.0f) ? 1.0f : 0.0f;
    v = v * (1.0f - spk);
    x = x * (1.0f - 0.025f) + spk;                // dt/tau_tr = 0.025

    g_state[idx] = j;
    g_state[3L * S_LAYER + idx] = v;
    g_state[6L * S_LAYER + idx] = x;

    if (L == 0) {                                 // ed1 = 0.5*x1 - 0.5*x_data@V0^T
        const int b = r >> 12, f = r & 4095;
        dout[(long)b * OUT_LD + 13312 + f] = 0.5f * x - g_c1h[r];
    } else if (L == 2) {                          // eg3 = 0.5*x3 - 0.5*y@W3^T
        const int b = r >> 12, f = r & 4095;
        dout[(long)b * OUT_LD + 9216 + f] = 0.5f * x - g_c2h[r];
    }
}

__global__ void zero_k(float* dout) {
    const long n1 = 9L * S_LAYER;
    const long n2 = 512L * OUT_LD;
    for (long i = (long)blockIdx.x * blockDim.x + threadIdx.x; i < n1 + n2;
         i += (long)gridDim.x * blockDim.x) {
        if (i < n1) g_state[i] = 0.0f;
        else        dout[i - n1] = 0.0f;
    }
}

// ---------------------------------------------------------------------------
static void gemm2(bool tb,
                  const float* A1, int lda1, const float* B1, int ldb1, int K1,
                  const float* A2, int lda2, const float* B2, int ldb2, int K2,
                  float* C, int ldc,
                  const float* a0, int l0, float g0,
                  const float* a1, int l1, float g1,
                  float alpha, int M, int N,
                  int kc = 0, int nsplit = 1, long czstride = 0) {
    GemmP p;
    p.A1 = A1; p.lda1 = lda1; p.B1 = B1; p.ldb1 = ldb1;
    p.A2 = A2; p.lda2 = lda2; p.B2 = B2; p.ldb2 = ldb2;
    p.K1 = K1; p.K2 = K2;
    p.C = C; p.ldc = ldc;
    p.aux0 = a0; p.ld0 = l0; p.g0 = g0;
    p.aux1 = a1; p.ld1 = l1; p.g1 = g1;
    p.alpha = alpha; p.kc = kc; p.czstride = czstride;
    dim3 grid(N / BN, M / BM, nsplit);
    if (tb) gemm_k<true><<<grid, 256>>>(p);
    else    gemm_k<false><<<grid, 256>>>(p);
}

extern "C" void kernel_launch(void* const* d_in, const int* in_sizes, int n_in,
                              void* d_out, int out_size) {
    (void)in_sizes; (void)n_in; (void)out_size;
    // input order: x_data, y_target, W0, V0, W1, V1, W2, V2, W3, V3, num_steps
    const float* xd = (const float*)d_in[0];   // (512, 1024)
    const float* yt = (const float*)d_in[1];   // (512, 512)
    const float* W0 = (const float*)d_in[2];   // (1024, 4096)
    const float* V0 = (const float*)d_in[3];   // (4096, 1024)
    const float* W1 = (const float*)d_in[4];   // (4096, 4096)
    const float* V1 = (const float*)d_in[5];   // (4096, 4096)
    const float* W2 = (const float*)d_in[6];   // (4096, 4096)
    const float* V2 = (const float*)d_in[7];   // (4096, 4096)
    const float* W3 = (const float*)d_in[8];   // (4096, 512)
    const float* V3 = (const float*)d_in[9];   // (512, 4096)
    float* out = (float*)d_out;                // (512, 26112)

    float *st = nullptr, *tin = nullptr, *c1h = nullptr, *c2h = nullptr;
    float *pA = nullptr, *pB = nullptr;
    cudaGetSymbolAddress((void**)&st,  g_state);
    cudaGetSymbolAddress((void**)&tin, g_tin);
    cudaGetSymbolAddress((void**)&c1h, g_c1h);
    cudaGetSymbolAddress((void**)&c2h, g_c2h);
    cudaGetSymbolAddress((void**)&pA,  g_pA);
    cudaGetSymbolAddress((void**)&pB,  g_pB);

    float* x1 = st + 6L * S_LAYER;
    float* x2 = st + 7L * S_LAYER;
    float* x3 = st + 8L * S_LAYER;
    float* t1 = tin;
    float* t2 = tin + S_LAYER;
    float* t3 = tin + 2L * S_LAYER;

    // error-tensor slices inside d_out (row stride OUT_LD)
    float* eg0 = out + 0;
    float* eg1 = out + 1024;
    float* eg2 = out + 5120;
    float* eg3 = out + 9216;     // written by lif_k
    float* ed1 = out + 13312;    // written by lif_k
    float* ed2 = out + 17408;
    float* ed3 = out + 21504;
    float* ed4 = out + 25600;

    // --- init: zero state + all error signals ---
    zero_k<<<2048, 256>>>(out);

    // --- step-invariant terms ---
    gemm2(true, xd, 1024, V0, 1024, 1024, nullptr, 0, nullptr, 0, 0,
          c1h, 4096, nullptr, 0, 0.f, nullptr, 0, 0.f, 0.5f, 512, 4096);
    gemm2(true, yt, 512, W3, 512, 512, nullptr, 0, nullptr, 0, 0,
          c2h, 4096, nullptr, 0, 0.f, nullptr, 0, 0.f, 0.5f, 512, 4096);

    const int NUM_STEPS = 25;
    for (int t = 0; t < NUM_STEPS; t++) {
        // ---------------- Phase A: injected currents (merged 2-segment K) ----
        // t1 = eg0@W0 + ed2@V1 - ed1 - eg1       (K = 1024 + 4096)
        gemm2(false, eg0, OUT_LD, W0, 4096, 1024,
                     ed2, OUT_LD, V1, 4096, 4096,
              t1, 4096, ed1, OUT_LD, -1.f, eg1, OUT_LD, -1.f, 1.f, 512, 4096);
        // t2 = eg1@W1 + ed3@V2 - ed2 - eg2       (K = 4096 + 4096)
        gemm2(false, eg1, OUT_LD, W1, 4096, 4096,
                     ed3, OUT_LD, V2, 4096, 4096,
              t2, 4096, ed2, OUT_LD, -1.f, eg2, OUT_LD, -1.f, 1.f, 512, 4096);
        // t3 = eg2@W2 + ed4@V3 - ed3 - eg3       (K = 4096 + 512)
        gemm2(false, eg2, OUT_LD, W2, 4096, 4096,
                     ed4, OUT_LD, V3, 4096, 512,
              t3, 4096, ed3, OUT_LD, -1.f, eg3, OUT_LD, -1.f, 1.f, 512, 4096);

        // ---------------- LIF update (+ ed1, eg3) ----------------
        lif_k<<<(3 * S_LAYER + 255) / 256, 256>>>(out);

        // ---------------- Phase B: error signals ----------------
        // eg1 = 0.5*x1 - 0.5*(x2 @ W1^T)
        gemm2(true, x2, 4096, W1, 4096, 4096, nullptr, 0, nullptr, 0, 0,
              eg1, OUT_LD, x1, 4096, 0.5f, nullptr, 0, 0.f, -0.5f, 512, 4096);
        // ed2 = 0.5*x2 - 0.5*(x1 @ V1^T)
        gemm2(true, x1, 4096, V1, 4096, 4096, nullptr, 0, nullptr, 0, 0,
              ed2, OUT_LD, x2, 4096, 0.5f, nullptr, 0, 0.f, -0.5f, 512, 4096);
        // eg2 = 0.5*x2 - 0.5*(x3 @ W2^T)
        gemm2(true, x3, 4096, W2, 4096, 4096, nullptr, 0, nullptr, 0, 0,
              eg2, OUT_LD, x2, 4096, 0.5f, nullptr, 0, 0.f, -0.5f, 512, 4096);
        // ed3 = 0.5*x3 - 0.5*(x2 @ V2^T)
        gemm2(true, x2, 4096, V2, 4096, 4096, nullptr, 0, nullptr, 0, 0,
              ed3, OUT_LD, x3, 4096, 0.5f, nullptr, 0, 0.f, -0.5f, 512, 4096);

        // eg0 = 0.5*x_data - 0.5*(x1 @ W0^T)   split-K 4x (N=1024, K=4096)
        gemm2(true, x1, 4096, W0, 4096, 4096, nullptr, 0, nullptr, 0, 0,
              pA, 1024, nullptr, 0, 0.f, nullptr, 0, 0.f, 1.f, 512, 1024,
              /*kc=*/1024, /*nsplit=*/4, /*czstride=*/(long)512 * 1024);
        reduce_k<<<(512 * 1024 + 255) / 256, 256>>>(pA, 4, xd, 1024, out, 0, 1024);

        // ed4 = 0.5*y - 0.5*(x3 @ V3^T)        split-K 8x (N=512, K=4096)
        gemm2(true, x3, 4096, V3, 4096, 4096, nullptr, 0, nullptr, 0, 0,
              pB, 512, nullptr, 0, 0.f, nullptr, 0, 0.f, 1.f, 512, 512,
              /*kc=*/512, /*nsplit=*/8, /*czstride=*/(long)512 * 512);
        reduce_k<<<(512 * 512 + 255) / 256, 256>>>(pB, 8, yt, 512, out, 25600, 512);
    }
}

// round 10
// speedup vs baseline: 1.9788x; 1.9788x over previous
#include <cuda_runtime.h>
#include <cuda_bf16.h>
#include <cstdint>

// ---------------------------------------------------------------------------
// bPC SNN, 25 steps. Round 10: legacy-HMMA (mma.sync bf16) emulated-fp32 GEMM.
// (Resubmission of R9 — infra "container failed twice", kernel never ran.)
//   - tcgen05 unavailable (harness targets compute_103 base, not sm_103a).
//     mma.sync.m16n8k16.bf16 / ldmatrix / cp.async are baseline sm_80+
//     features and run on Blackwell tensor cores as HMMA.
//   - Numerics: bf16x3 exact split, 6 products (hh,hm,mh,hl,lh,mm) into fp32
//     accumulators -> ~fp32 accuracy (dropped terms ~2^-27).
//   - GEMM: 128x128 tile, BK=32, 8 warps x (64x32), cp.async depth-2
//     pipeline, 80B-pitch smem (ldmatrix conflict-free), fused epilogue
//     C = alpha*AB + g0*aux0 + g1*aux1. Two-segment K merges Phase-A pairs.
//   - Weights pre-split once per launch (both orientations); activations
//     split per step. Errors live directly in d_out (row stride 26112).
// ---------------------------------------------------------------------------

#define S_LAYER (512 * 4096)
#define OUT_LD  26112

typedef __nv_bfloat16 bf16;

// ---- device storage (allocation-free scratch) -----------------------------
__device__ float g_state[9 * S_LAYER];          // j1..3 | v1..3 | x1..3
__device__ float g_tin[3 * S_LAYER];            // injected currents
__device__ float g_c1h[S_LAYER];                // 0.5 * x_data @ V0^T
__device__ float g_c2h[S_LAYER];                // 0.5 * y_target @ W3^T
__device__ bf16  g_w[459276288];                // weight splits (direct+T), x3
__device__ bf16  g_act[27525120];               // activation splits, x3
__device__ bf16  g_io[2359296];                 // xd/yt splits, x3

// ---- weight slab offsets (elements) ---------------------------------------
#define OFF_W0d   0L
#define OFF_V0d   12582912L
#define OFF_W1d   25165824L
#define OFF_V1d   75497472L
#define OFF_W2d   125829120L
#define OFF_V2d   176160768L
#define OFF_W3d   226492416L
#define OFF_V3d   232783872L
#define OFF_Wt0   239075328L
#define OFF_Wt1   251658240L
#define OFF_Vt1   301989888L
#define OFF_Wt2   352321536L
#define OFF_Vt2   402653184L
#define OFF_Vt3   452984832L

// activation slab offsets (elements)
#define AOFF_EG0  0L
#define AOFF_EG1  1572864L
#define AOFF_EG2  7864320L
#define AOFF_ED2  14155776L
#define AOFF_ED3  20447232L
#define AOFF_ED4  26738688L
#define AOFF_X1   0L
#define AOFF_X2   6291456L
#define AOFF_X3   12582912L

// ---------------------------------------------------------------------------
// PTX helpers (baseline sm_80 features only)
// ---------------------------------------------------------------------------
__device__ __forceinline__ uint32_t smem_u32(const void* p) {
    uint32_t a;
    asm("{ .reg .u64 t; cvta.to.shared.u64 t, %1; cvt.u32.u64 %0, t; }"
        : "=r"(a) : "l"(p));
    return a;
}
#define CP16(dst, src) \
    asm volatile("cp.async.cg.shared.global [%0], [%1], 16;" \
                 :: "r"(dst), "l"(src) : "memory")
#define CP_COMMIT() asm volatile("cp.async.commit_group;" ::: "memory")
#define CP_WAIT1()  asm volatile("cp.async.wait_group 1;" ::: "memory")
#define CP_WAIT0()  asm volatile("cp.async.wait_group 0;" ::: "memory")

__device__ __forceinline__ void ldsm_x4(uint32_t (&r)[4], uint32_t addr) {
    asm volatile("ldmatrix.sync.aligned.m8n8.x4.shared.b16 {%0,%1,%2,%3}, [%4];"
                 : "=r"(r[0]), "=r"(r[1]), "=r"(r[2]), "=r"(r[3]) : "r"(addr));
}
__device__ __forceinline__ void mma_bf16(float (&c)[4], const uint32_t (&a)[4],
                                         uint32_t b0, uint32_t b1) {
    asm volatile(
        "mma.sync.aligned.m16n8k16.row.col.f32.bf16.bf16.f32 "
        "{%0,%1,%2,%3}, {%4,%5,%6,%7}, {%8,%9}, {%0,%1,%2,%3};"
        : "+f"(c[0]), "+f"(c[1]), "+f"(c[2]), "+f"(c[3])
        : "r"(a[0]), "r"(a[1]), "r"(a[2]), "r"(a[3]), "r"(b0), "r"(b1));
}

// ---------------------------------------------------------------------------
// GEMM kernel. C[512, N] = alpha * sum6( A_s @ B_s^T ) + g0*aux0 + g1*aux1
// A slabs: [3][512][K] bf16 splits (k-contiguous). B slabs: [3][N][K] bf16.
// Two K segments (A1/B1 for K1, then A2/B2 for K2), K1/K2 multiples of 32.
// ---------------------------------------------------------------------------
struct TG {
    const bf16 *A1, *B1, *A2, *B2;
    long sA1, sB1, sA2, sB2;      // split strides (elements)
    int  K1, K2;
    float* C; int ldc;
    const float* aux0; int ld0; float g0;
    const float* aux1; int ld1; float g1;
    float alpha;
};

// smem tile: 128 rows x 80 bytes (32 bf16 + 8 pad) = 10240 B
#define TILE_B   10240
#define STAGE_B  (6 * TILE_B)     // 3 A-splits + 3 B-splits
#define SMEM_MM  (2 * STAGE_B)    // double buffered = 122880 B

__global__ __launch_bounds__(256, 1) void gemm_mma(TG p) {
    extern __shared__ char smem[];
    const uint32_t sb = smem_u32(smem);
    const int tid  = threadIdx.x;
    const int wid  = tid >> 5;
    const int lane = tid & 31;
    const int bm   = blockIdx.y * 128;
    const int bn   = blockIdx.x * 128;
    const int wm   = (wid & 1) * 64;        // warp m-offset in tile
    const int wn   = (wid >> 1) * 32;       // warp n-offset in tile

    const int nk1 = p.K1 >> 5;
    const int nk  = (p.K1 + p.K2) >> 5;

    float acc[4][4][4];
#pragma unroll
    for (int i = 0; i < 4; i++)
#pragma unroll
        for (int j = 0; j < 4; j++)
#pragma unroll
            for (int q = 0; q < 4; q++) acc[i][j][q] = 0.0f;

    // ---- async loader: one 128x32 tile per split, 512 16B transfers -------
    auto load_chunk = [&](int c, int s) {
        const bool seg2 = (c >= nk1);
        const bf16* Ab = seg2 ? p.A2 : p.A1;
        const bf16* Bb = seg2 ? p.B2 : p.B1;
        const long  sA = seg2 ? p.sA2 : p.sA1;
        const long  sB = seg2 ? p.sB2 : p.sB1;
        const int   Kl = seg2 ? (p.K2) : (p.K1);
        const long  kc = (long)(seg2 ? c - nk1 : c) * 32;
        const uint32_t base = sb + s * STAGE_B;
#pragma unroll
        for (int t3 = 0; t3 < 3; t3++) {
            const bf16* ga = Ab + t3 * sA + kc;
            const bf16* gb = Bb + t3 * sB + kc;
#pragma unroll
            for (int i = 0; i < 2; i++) {
                const int id  = tid + i * 256;
                const int row = id >> 2;
                const int seg = (id & 3) * 16;      // byte offset within row
                CP16(base + t3 * TILE_B + row * 80 + seg,
                     (const char*)(ga + (long)(bm + row) * Kl) + seg);
                CP16(base + (3 + t3) * TILE_B + row * 80 + seg,
                     (const char*)(gb + (long)(bn + row) * Kl) + seg);
            }
        }
        CP_COMMIT();
    };

    // product order: (a-split, b-split) = hh, hm, mh, hl, lh, mm
    const int pa[6] = {0, 0, 1, 0, 2, 1};
    const int pb[6] = {0, 1, 0, 2, 0, 1};

    load_chunk(0, 0);

    for (int c = 0; c < nk; c++) {
        const int s = c & 1;
        if (c + 1 < nk) { load_chunk(c + 1, s ^ 1); CP_WAIT1(); }
        else           { CP_WAIT0(); }
        __syncthreads();

        const uint32_t base = sb + s * STAGE_B;
#pragma unroll
        for (int pi = 0; pi < 6; pi++) {
            const uint32_t ab = base + pa[pi] * TILE_B;
            const uint32_t bb = base + (3 + pb[pi]) * TILE_B;
#pragma unroll
            for (int kk = 0; kk < 2; kk++) {
                uint32_t a[4][4], bq[2][4];
#pragma unroll
                for (int i = 0; i < 4; i++) {
                    const uint32_t addr = ab
                        + (uint32_t)(wm + 16 * i + (lane & 15)) * 80
                        + kk * 32 + (lane >> 4) * 16;
                    ldsm_x4(a[i], addr);
                }
#pragma unroll
                for (int h = 0; h < 2; h++) {
                    const uint32_t addr = bb
                        + (uint32_t)(wn + 16 * h + 8 * ((lane >> 4) & 1) + (lane & 7)) * 80
                        + kk * 32 + ((lane >> 3) & 1) * 16;
                    ldsm_x4(bq[h], addr);
                }
#pragma unroll
                for (int i = 0; i < 4; i++)
#pragma unroll
                    for (int j = 0; j < 4; j++)
                        mma_bf16(acc[i][j], a[i],
                                 bq[j >> 1][(j & 1) * 2],
                                 bq[j >> 1][(j & 1) * 2 + 1]);
            }
        }
        __syncthreads();
    }

    // ---- epilogue ---------------------------------------------------------
    const int r0    = lane >> 2;
    const int cpair = (lane & 3) * 2;
#pragma unroll
    for (int i = 0; i < 4; i++) {
        const long gr = bm + wm + 16 * i + r0;
#pragma unroll
        for (int j = 0; j < 4; j++) {
            const int gc = bn + wn + 8 * j + cpair;
            float v0 = p.alpha * acc[i][j][0];
            float v1 = p.alpha * acc[i][j][1];
            float v2 = p.alpha * acc[i][j][2];
            float v3 = p.alpha * acc[i][j][3];
            if (p.aux0) {
                const float2 u0 = *(const float2*)(p.aux0 + gr * p.ld0 + gc);
                const float2 u1 = *(const float2*)(p.aux0 + (gr + 8) * p.ld0 + gc);
                v0 += p.g0 * u0.x; v1 += p.g0 * u0.y;
                v2 += p.g0 * u1.x; v3 += p.g0 * u1.y;
            }
            if (p.aux1) {
                const float2 u0 = *(const float2*)(p.aux1 + gr * p.ld1 + gc);
                const float2 u1 = *(const float2*)(p.aux1 + (gr + 8) * p.ld1 + gc);
                v0 += p.g1 * u0.x; v1 += p.g1 * u0.y;
                v2 += p.g1 * u1.x; v3 += p.g1 * u1.y;
            }
            *(float2*)(p.C + gr * p.ldc + gc)       = make_float2(v0, v1);
            *(float2*)(p.C + (gr + 8) * p.ldc + gc) = make_float2(v2, v3);
        }
    }
}

// ---------------------------------------------------------------------------
// bf16x3 splitters
// ---------------------------------------------------------------------------
__global__ void split_k(const float* __restrict__ in, int ld, int rows, int cols,
                        bf16* __restrict__ out) {
    const long n = (long)rows * cols;
    const long idx = (long)blockIdx.x * blockDim.x + threadIdx.x;
    if (idx >= n) return;
    const int r = (int)(idx / cols), c = (int)(idx - (long)r * cols);
    const float a = in[(long)r * ld + c];
    const bf16 h = __float2bfloat16(a);
    const float f1 = a - __bfloat162float(h);
    const bf16 m = __float2bfloat16(f1);
    const float f2 = f1 - __bfloat162float(m);
    const bf16 l = __float2bfloat16(f2);
    out[idx] = h; out[n + idx] = m; out[2 * n + idx] = l;
}

// transposed weight split: out[s][n][k] = split_s( in[k*ldin + n] )
__global__ void splitT_k(const float* __restrict__ in, int ldin, int K, int N,
                         bf16* __restrict__ out) {
    const long n = (long)N * K;
    const long idx = (long)blockIdx.x * blockDim.x + threadIdx.x;
    if (idx >= n) return;
    const int nn = (int)(idx / K), k = (int)(idx - (long)nn * K);
    const float a = in[(long)k * ldin + nn];
    const bf16 h = __float2bfloat16(a);
    const float f1 = a - __bfloat162float(h);
    const bf16 m = __float2bfloat16(f1);
    const float f2 = f1 - __bfloat162float(m);
    const bf16 l = __float2bfloat16(f2);
    out[idx] = h; out[n + idx] = m; out[2 * n + idx] = l;
}

// ---------------------------------------------------------------------------
// LIF update (+ ed1, eg3 emission)
// ---------------------------------------------------------------------------
__global__ void lif_k(float* dout) {
    const long idx = (long)blockIdx.x * blockDim.x + threadIdx.x;
    if (idx >= 3L * S_LAYER) return;
    const int L = (int)(idx / S_LAYER);
    const int r = (int)(idx - (long)L * S_LAYER);

    const float tin = g_tin[idx];
    float j = g_state[idx];
    float v = g_state[3L * S_LAYER + idx];
    float x = g_state[6L * S_LAYER + idx];

    j = j + 0.25f * (tin - j);
    v = v + 0.05f * (j - v);
    const float spk = (v > 1.0f) ? 1.0f : 0.0f;
    v = v * (1.0f - spk);
    x = x * (1.0f - 0.025f) + spk;

    g_state[idx] = j;
    g_state[3L * S_LAYER + idx] = v;
    g_state[6L * S_LAYER + idx] = x;

    if (L == 0) {
        const int b = r >> 12, f = r & 4095;
        dout[(long)b * OUT_LD + 13312 + f] = 0.5f * x - g_c1h[r];
    } else if (L == 2) {
        const int b = r >> 12, f = r & 4095;
        dout[(long)b * OUT_LD + 9216 + f] = 0.5f * x - g_c2h[r];
    }
}

__global__ void zero_k(float* dout) {
    const long n1 = 9L * S_LAYER;
    const long n2 = 512L * OUT_LD;
    for (long i = (long)blockIdx.x * blockDim.x + threadIdx.x; i < n1 + n2;
         i += (long)gridDim.x * blockDim.x) {
        if (i < n1) g_state[i] = 0.0f;
        else        dout[i - n1] = 0.0f;
    }
}

// ---------------------------------------------------------------------------
static void tgemm(const bf16* A1, long sA1, const bf16* B1, long sB1, int K1,
                  const bf16* A2, long sA2, const bf16* B2, long sB2, int K2,
                  float* C, int ldc,
                  const float* a0, int l0, float g0,
                  const float* a1, int l1, float g1,
                  float alpha, int N) {
    TG p;
    p.A1 = A1; p.sA1 = sA1; p.B1 = B1; p.sB1 = sB1; p.K1 = K1;
    p.A2 = A2 ? A2 : A1; p.sA2 = sA2; p.B2 = B2 ? B2 : B1; p.sB2 = sB2; p.K2 = K2;
    p.C = C; p.ldc = ldc;
    p.aux0 = a0; p.ld0 = l0; p.g0 = g0;
    p.aux1 = a1; p.ld1 = l1; p.g1 = g1;
    p.alpha = alpha;
    dim3 grid(N / 128, 4);
    gemm_mma<<<grid, 256, SMEM_MM>>>(p);
}

static void split(const float* in, int ld, int rows, int cols, bf16* out) {
    const long n = (long)rows * cols;
    split_k<<<(int)((n + 255) / 256), 256>>>(in, ld, rows, cols, out);
}

extern "C" void kernel_launch(void* const* d_in, const int* in_sizes, int n_in,
                              void* d_out, int out_size) {
    (void)in_sizes; (void)n_in; (void)out_size;
    const float* xd = (const float*)d_in[0];
    const float* yt = (const float*)d_in[1];
    const float* W0 = (const float*)d_in[2];
    const float* V0 = (const float*)d_in[3];
    const float* W1 = (const float*)d_in[4];
    const float* V1 = (const float*)d_in[5];
    const float* W2 = (const float*)d_in[6];
    const float* V2 = (const float*)d_in[7];
    const float* W3 = (const float*)d_in[8];
    const float* V3 = (const float*)d_in[9];
    float* out = (float*)d_out;

    cudaFuncSetAttribute(gemm_mma, cudaFuncAttributeMaxDynamicSharedMemorySize, SMEM_MM);

    float *st, *tin, *c1h, *c2h; bf16 *w, *act, *io;
    cudaGetSymbolAddress((void**)&st,  g_state);
    cudaGetSymbolAddress((void**)&tin, g_tin);
    cudaGetSymbolAddress((void**)&c1h, g_c1h);
    cudaGetSymbolAddress((void**)&c2h, g_c2h);
    cudaGetSymbolAddress((void**)&w,   g_w);
    cudaGetSymbolAddress((void**)&act, g_act);
    cudaGetSymbolAddress((void**)&io,  g_io);

    float* x1 = st + 6L * S_LAYER;
    float* x2 = st + 7L * S_LAYER;
    float* x3 = st + 8L * S_LAYER;
    float* t1 = tin;
    float* t2 = tin + S_LAYER;
    float* t3 = tin + 2L * S_LAYER;

    float* eg0 = out + 0;
    float* eg1 = out + 1024;
    float* eg2 = out + 5120;
    float* eg3 = out + 9216;     // written by lif_k
    float* ed1 = out + 13312;    // written by lif_k
    float* ed2 = out + 17408;
    float* ed3 = out + 21504;
    float* ed4 = out + 25600;

    zero_k<<<2048, 256>>>(out);

    // ---- weight splits (once per launch, deterministic) ----
    split(W0, 4096, 1024, 4096, w + OFF_W0d);
    split(V0, 1024, 4096, 1024, w + OFF_V0d);
    split(W1, 4096, 4096, 4096, w + OFF_W1d);
    split(V1, 4096, 4096, 4096, w + OFF_V1d);
    split(W2, 4096, 4096, 4096, w + OFF_W2d);
    split(V2, 4096, 4096, 4096, w + OFF_V2d);
    split(W3, 512,  4096, 512,  w + OFF_W3d);
    split(V3, 4096, 512,  4096, w + OFF_V3d);
    splitT_k<<<(4096 * 1024 + 255) / 256, 256>>>(W0, 4096, 1024, 4096, w + OFF_Wt0);
    splitT_k<<<(4096 * 4096 + 255) / 256, 256>>>(W1, 4096, 4096, 4096, w + OFF_Wt1);
    splitT_k<<<(4096 * 4096 + 255) / 256, 256>>>(V1, 4096, 4096, 4096, w + OFF_Vt1);
    splitT_k<<<(4096 * 4096 + 255) / 256, 256>>>(W2, 4096, 4096, 4096, w + OFF_Wt2);
    splitT_k<<<(4096 * 4096 + 255) / 256, 256>>>(V2, 4096, 4096, 4096, w + OFF_Vt2);
    splitT_k<<<(4096 * 512  + 255) / 256, 256>>>(V3, 4096, 512,  4096, w + OFF_Vt3);
    split(xd, 1024, 512, 1024, io);                 // xd splits
    split(yt, 512,  512, 512,  io + 1572864);       // yt splits

    // ---- step-invariant terms ----
    // c1h = 0.5 * xd @ V0^T   (N=4096, K=1024)
    tgemm(io, 512L * 1024, w + OFF_V0d, 4096L * 1024, 1024,
          nullptr, 0, nullptr, 0, 0,
          c1h, 4096, nullptr, 0, 0.f, nullptr, 0, 0.f, 0.5f, 4096);
    // c2h = 0.5 * yt @ W3^T   (N=4096, K=512)
    tgemm(io + 1572864, 512L * 512, w + OFF_W3d, 4096L * 512, 512,
          nullptr, 0, nullptr, 0, 0,
          c2h, 4096, nullptr, 0, 0.f, nullptr, 0, 0.f, 0.5f, 4096);

    const int NUM_STEPS = 25;
    for (int t = 0; t < NUM_STEPS; t++) {
        // ---- split phase-A inputs (pre-update errors) ----
        split(eg0, OUT_LD, 512, 1024, act + AOFF_EG0);
        split(eg1, OUT_LD, 512, 4096, act + AOFF_EG1);
        split(eg2, OUT_LD, 512, 4096, act + AOFF_EG2);
        split(ed2, OUT_LD, 512, 4096, act + AOFF_ED2);
        split(ed3, OUT_LD, 512, 4096, act + AOFF_ED3);
        split(ed4, OUT_LD, 512, 512,  act + AOFF_ED4);

        // ---- Phase A: injected currents (2-segment K) ----
        // t1 = eg0@W0 + ed2@V1 - ed1 - eg1
        tgemm(act + AOFF_EG0, 512L * 1024, w + OFF_Wt0, 4096L * 1024, 1024,
              act + AOFF_ED2, 512L * 4096, w + OFF_Vt1, 4096L * 4096, 4096,
              t1, 4096, ed1, OUT_LD, -1.f, eg1, OUT_LD, -1.f, 1.f, 4096);
        // t2 = eg1@W1 + ed3@V2 - ed2 - eg2
        tgemm(act + AOFF_EG1, 512L * 4096, w + OFF_Wt1, 4096L * 4096, 4096,
              act + AOFF_ED3, 512L * 4096, w + OFF_Vt2, 4096L * 4096, 4096,
              t2, 4096, ed2, OUT_LD, -1.f, eg2, OUT_LD, -1.f, 1.f, 4096);
        // t3 = eg2@W2 + ed4@V3 - ed3 - eg3
        tgemm(act + AOFF_EG2, 512L * 4096, w + OFF_Wt2, 4096L * 4096, 4096,
              act + AOFF_ED4, 512L * 512,  w + OFF_Vt3, 4096L * 512,  512,
              t3, 4096, ed3, OUT_LD, -1.f, eg3, OUT_LD, -1.f, 1.f, 4096);

        // ---- LIF update (+ ed1, eg3) ----
        lif_k<<<(3 * S_LAYER + 255) / 256, 256>>>(out);

        // ---- split traces ----
        split(x1, 4096, 512, 4096, act + AOFF_X1);
        split(x2, 4096, 512, 4096, act + AOFF_X2);
        split(x3, 4096, 512, 4096, act + AOFF_X3);

        // ---- Phase B: error signals ----
        // eg0 = 0.5*xd - 0.5*(x1 @ W0^T)   N=1024 K=4096
        tgemm(act + AOFF_X1, 512L * 4096, w + OFF_W0d, 1024L * 4096, 4096,
              nullptr, 0, nullptr, 0, 0,
              eg0, OUT_LD, xd, 1024, 0.5f, nullptr, 0, 0.f, -0.5f, 1024);
        // eg1 = 0.5*x1 - 0.5*(x2 @ W1^T)
        tgemm(act + AOFF_X2, 512L * 4096, w + OFF_W1d, 4096L * 4096, 4096,
              nullptr, 0, nullptr, 0, 0,
              eg1, OUT_LD, x1, 4096, 0.5f, nullptr, 0, 0.f, -0.5f, 4096);
        // ed2 = 0.5*x2 - 0.5*(x1 @ V1^T)
        tgemm(act + AOFF_X1, 512L * 4096, w + OFF_V1d, 4096L * 4096, 4096,
              nullptr, 0, nullptr, 0, 0,
              ed2, OUT_LD, x2, 4096, 0.5f, nullptr, 0, 0.f, -0.5f, 4096);
        // eg2 = 0.5*x2 - 0.5*(x3 @ W2^T)
        tgemm(act + AOFF_X3, 512L * 4096, w + OFF_W2d, 4096L * 4096, 4096,
              nullptr, 0, nullptr, 0, 0,
              eg2, OUT_LD, x2, 4096, 0.5f, nullptr, 0, 0.f, -0.5f, 4096);
        // ed3 = 0.5*x3 - 0.5*(x2 @ V2^T)
        tgemm(act + AOFF_X2, 512L * 4096, w + OFF_V2d, 4096L * 4096, 4096,
              nullptr, 0, nullptr, 0, 0,
              ed3, OUT_LD, x3, 4096, 0.5f, nullptr, 0, 0.f, -0.5f, 4096);
        // ed4 = 0.5*yt - 0.5*(x3 @ V3^T)   N=512 K=4096
        tgemm(act + AOFF_X3, 512L * 4096, w + OFF_V3d, 512L * 4096, 4096,
              nullptr, 0, nullptr, 0, 0,
              ed4, OUT_LD, yt, 512, 0.5f, nullptr, 0, 0.f, -0.5f, 512);
    }
}

// round 13
// speedup vs baseline: 2.4216x; 1.2238x over previous
#include <cuda_runtime.h>
#include <cuda_bf16.h>
#include <cstdint>

// ---------------------------------------------------------------------------
// bPC SNN, 25 steps. Round 13: HMMA bf16x3 6-product GEMM (proven numerics)
// + structural fusions. (Byte-identical resubmit of R12 — broker container
// failed twice before compile; same flake as R9, where identical resubmit
// then passed and won.)
//   - bf16x3 / 6 products (hh,hm,mh,hl,lh,mm), fp32 accumulate: R10-proven
//     numerics (rel_err 5.27e-6). bf16x2 proved chaotic (R11, rel_err 1.05).
//   - Structural wins kept: fused split emission (GEMM epilogue / reduce_k /
//     lif_k -> zero per-step split kernels), split-K 4x/8x for eg0/ed4,
//     fragment-sharing 6-product inner loop (18 ldsm/kk vs 36).
//   - Depth-2 cp.async pipeline and smem layout identical to proven R10.
// ---------------------------------------------------------------------------

#define S_LAYER (512 * 4096)
#define OUT_LD  26112

typedef __nv_bfloat16 bf16;

// ---- device storage -------------------------------------------------------
__device__ float g_state[9 * S_LAYER];          // j1..3 | v1..3 | x1..3
__device__ float g_tin[3 * S_LAYER];            // injected currents
__device__ float g_c1h[S_LAYER];                // 0.5 * x_data @ V0^T
__device__ float g_c2h[S_LAYER];                // 0.5 * y_target @ W3^T
__device__ bf16  g_w[459276288];                // weight splits (direct+T), x3
__device__ bf16  g_act[46399488];               // activation splits, x3
__device__ bf16  g_io[2359296];                 // xd/yt splits, x3
__device__ float g_pA[4 * 512 * 1024];          // eg0 split-K partials
__device__ float g_pB[8 * 512 * 512];           // ed4 split-K partials

// ---- weight slab offsets (elements); each slab = [3][N][K] ----------------
#define OFF_W0d   0L            // [1024,4096]
#define OFF_V0d   12582912L     // [4096,1024]
#define OFF_W1d   25165824L     // [4096,4096]
#define OFF_V1d   75497472L
#define OFF_W2d   125829120L
#define OFF_V2d   176160768L
#define OFF_W3d   226492416L    // [4096,512]
#define OFF_V3d   232783872L    // [512,4096]
#define OFF_Wt0   239075328L    // [4096,1024]
#define OFF_Wt1   251658240L    // [4096,4096]
#define OFF_Vt1   301989888L
#define OFF_Wt2   352321536L
#define OFF_Vt2   402653184L
#define OFF_Vt3   452984832L    // [4096,512]

// activation slab offsets; each slab = [3][512][K]
#define AOFF_EG0  0L            // [512,1024]
#define AOFF_EG1  1572864L      // [512,4096]
#define AOFF_ED2  7864320L
#define AOFF_EG2  14155776L
#define AOFF_ED3  20447232L
#define AOFF_ED4  26738688L     // [512,512]
#define AOFF_X1   27525120L     // [512,4096]
#define AOFF_X2   33816576L
#define AOFF_X3   40108032L

// ---------------------------------------------------------------------------
__device__ __forceinline__ uint32_t smem_u32(const void* p) {
    uint32_t a;
    asm("{ .reg .u64 t; cvta.to.shared.u64 t, %1; cvt.u32.u64 %0, t; }"
        : "=r"(a) : "l"(p));
    return a;
}
#define CP16(dst, src) \
    asm volatile("cp.async.cg.shared.global [%0], [%1], 16;" \
                 :: "r"(dst), "l"(src) : "memory")
#define CP_COMMIT() asm volatile("cp.async.commit_group;" ::: "memory")
#define CP_WAIT1()  asm volatile("cp.async.wait_group 1;" ::: "memory")
#define CP_WAIT0()  asm volatile("cp.async.wait_group 0;" ::: "memory")

__device__ __forceinline__ void ldsm_x4(uint32_t (&r)[4], uint32_t addr) {
    asm volatile("ldmatrix.sync.aligned.m8n8.x4.shared.b16 {%0,%1,%2,%3}, [%4];"
                 : "=r"(r[0]), "=r"(r[1]), "=r"(r[2]), "=r"(r[3]) : "r"(addr));
}
__device__ __forceinline__ void mma_bf16(float (&c)[4], const uint32_t (&a)[4],
                                         uint32_t b0, uint32_t b1) {
    asm volatile(
        "mma.sync.aligned.m16n8k16.row.col.f32.bf16.bf16.f32 "
        "{%0,%1,%2,%3}, {%4,%5,%6,%7}, {%8,%9}, {%0,%1,%2,%3};"
        : "+f"(c[0]), "+f"(c[1]), "+f"(c[2]), "+f"(c[3])
        : "r"(a[0]), "r"(a[1]), "r"(a[2]), "r"(a[3]), "r"(b0), "r"(b1));
}

// ---------------------------------------------------------------------------
// GEMM: C[512,N] = alpha * sum6( A_s @ B_s^T ) + g0*aux0 + g1*aux1
//       (+ optional bf16x3 split emission of C, + optional split-K)
// A slabs: [3][512][*] bf16, k-contiguous rows. B slabs: [3][N][*] bf16.
// ---------------------------------------------------------------------------
struct TG {
    const bf16 *A1, *B1, *A2, *B2;
    long sA1, sB1, sA2, sB2;        // per-split slab strides
    int  lda1, ldb1, lda2, ldb2;    // row strides (elements)
    int  K1, K2;
    float* C; int ldc;
    const float* aux0; int ld0; float g0;
    const float* aux1; int ld1; float g1;
    float alpha;
    bf16* so; long sso; int ldso;   // optional split output [3][512][N]
    int  kc; long czstride;         // split-K: chunk len / C z-stride
};

#define TILE_B   10240            // 128 rows x 80B (32 bf16 + 8B pad)
#define STAGE_B  (6 * TILE_B)     // A0,A1,A2,B0,B1,B2
#define SMEM_MM  (2 * STAGE_B)    // double buffered = 122880 B

__global__ __launch_bounds__(256, 1) void gemm_mma(TG p) {
    extern __shared__ char smem[];
    const uint32_t sb = smem_u32(smem);
    const int tid  = threadIdx.x;
    const int wid  = tid >> 5;
    const int lane = tid & 31;
    const int bm   = blockIdx.y * 128;
    const int bn   = blockIdx.x * 128;
    const int wm   = (wid & 1) * 64;
    const int wn   = (wid >> 1) * 32;

    const bf16* LA1 = p.A1;
    const bf16* LB1 = p.B1;
    int    LK1 = p.K1;
    float* C   = p.C;
    if (p.kc) {
        LA1 += (long)blockIdx.z * p.kc;
        LB1 += (long)blockIdx.z * p.kc;
        LK1  = p.kc;
        C   += (long)blockIdx.z * p.czstride;
    }
    const int nk1 = LK1 >> 5;
    const int nk  = (LK1 + p.K2) >> 5;

    float acc[4][4][4];
#pragma unroll
    for (int i = 0; i < 4; i++)
#pragma unroll
        for (int j = 0; j < 4; j++)
#pragma unroll
            for (int q = 0; q < 4; q++) acc[i][j][q] = 0.0f;

    auto load_chunk = [&](int c, int s) {
        const bool seg2 = (c >= nk1);
        const bf16* Ab = seg2 ? p.A2 : LA1;
        const bf16* Bb = seg2 ? p.B2 : LB1;
        const long  sA = seg2 ? p.sA2 : p.sA1;
        const long  sB = seg2 ? p.sB2 : p.sB1;
        const int   la = seg2 ? p.lda2 : p.lda1;
        const int   lb = seg2 ? p.ldb2 : p.ldb1;
        const long  kcoff = (long)(seg2 ? c - nk1 : c) * 32;
        const uint32_t base = sb + s * STAGE_B;
#pragma unroll
        for (int sp = 0; sp < 3; sp++) {
            const bf16* ga = Ab + sp * sA + kcoff;
            const bf16* gb = Bb + sp * sB + kcoff;
#pragma unroll
            for (int i = 0; i < 2; i++) {
                const int id  = tid + i * 256;
                const int row = id >> 2;
                const int seg = (id & 3) * 16;
                CP16(base + sp * TILE_B + row * 80 + seg,
                     (const char*)(ga + (long)(bm + row) * la) + seg);
                CP16(base + (3 + sp) * TILE_B + row * 80 + seg,
                     (const char*)(gb + (long)(bn + row) * lb) + seg);
            }
        }
        CP_COMMIT();
    };

    load_chunk(0, 0);

#define LDA(F, abase, kk)                                                      \
    _Pragma("unroll")                                                          \
    for (int i = 0; i < 4; i++)                                                \
        ldsm_x4(F[i], (abase) + (uint32_t)(wm + 16 * i + (lane & 15)) * 80     \
                        + (kk) * 32 + (lane >> 4) * 16);
#define LDB(F, bbase, kk)                                                      \
    _Pragma("unroll")                                                          \
    for (int h = 0; h < 2; h++)                                                \
        ldsm_x4(F[h], (bbase) + (uint32_t)(wn + 16 * h + 8 * ((lane >> 4) & 1) \
                        + (lane & 7)) * 80 + (kk) * 32 + ((lane >> 3) & 1) * 16);
#define MMAS(AF, BF)                                                           \
    _Pragma("unroll")                                                          \
    for (int i = 0; i < 4; i++)                                                \
        _Pragma("unroll")                                                      \
        for (int j = 0; j < 4; j++)                                            \
            mma_bf16(acc[i][j], AF[i], BF[j >> 1][(j & 1) * 2],                \
                     BF[j >> 1][(j & 1) * 2 + 1]);

    for (int c = 0; c < nk; c++) {
        const int s = c & 1;
        if (c + 1 < nk) { load_chunk(c + 1, s ^ 1); CP_WAIT1(); }
        else           { CP_WAIT0(); }
        __syncthreads();

        const uint32_t base = sb + s * STAGE_B;
        const uint32_t a0 = base,              a1 = base + TILE_B,     a2 = base + 2 * TILE_B;
        const uint32_t b0 = base + 3 * TILE_B, b1 = base + 4 * TILE_B, b2 = base + 5 * TILE_B;
#pragma unroll
        for (int kk = 0; kk < 2; kk++) {
            uint32_t Ah[4][4], Am[4][4], Al[4][4], Bh[2][4], Bm[2][4], Bl[2][4];
            LDA(Ah, a0, kk); LDB(Bh, b0, kk);
            MMAS(Ah, Bh);                       // hi * hi
            LDB(Bm, b1, kk);
            MMAS(Ah, Bm);                       // hi * mid
            LDA(Am, a1, kk);
            MMAS(Am, Bh);                       // mid * hi
            LDB(Bl, b2, kk);
            MMAS(Ah, Bl);                       // hi * lo
            LDA(Al, a2, kk);
            MMAS(Al, Bh);                       // lo * hi
            MMAS(Am, Bm);                       // mid * mid
        }
        __syncthreads();
    }
#undef LDA
#undef LDB
#undef MMAS

    // ---- epilogue ---------------------------------------------------------
    const int r0    = lane >> 2;
    const int cpair = (lane & 3) * 2;
#pragma unroll
    for (int i = 0; i < 4; i++) {
        const long gr = bm + wm + 16 * i + r0;
#pragma unroll
        for (int j = 0; j < 4; j++) {
            const int gc = bn + wn + 8 * j + cpair;
            float v[4];
            v[0] = p.alpha * acc[i][j][0];
            v[1] = p.alpha * acc[i][j][1];
            v[2] = p.alpha * acc[i][j][2];
            v[3] = p.alpha * acc[i][j][3];
            if (p.aux0) {
                const float2 u0 = *(const float2*)(p.aux0 + gr * p.ld0 + gc);
                const float2 u1 = *(const float2*)(p.aux0 + (gr + 8) * p.ld0 + gc);
                v[0] += p.g0 * u0.x; v[1] += p.g0 * u0.y;
                v[2] += p.g0 * u1.x; v[3] += p.g0 * u1.y;
            }
            if (p.aux1) {
                const float2 u0 = *(const float2*)(p.aux1 + gr * p.ld1 + gc);
                const float2 u1 = *(const float2*)(p.aux1 + (gr + 8) * p.ld1 + gc);
                v[0] += p.g1 * u0.x; v[1] += p.g1 * u0.y;
                v[2] += p.g1 * u1.x; v[3] += p.g1 * u1.y;
            }
            *(float2*)(C + gr * p.ldc + gc)       = make_float2(v[0], v[1]);
            *(float2*)(C + (gr + 8) * p.ldc + gc) = make_float2(v[2], v[3]);
            if (p.so) {                         // fused bf16x3 split emission
                bf16 h[4], m[4], l[4];
#pragma unroll
                for (int q = 0; q < 4; q++) {
                    h[q] = __float2bfloat16(v[q]);
                    const float r1 = v[q] - __bfloat162float(h[q]);
                    m[q] = __float2bfloat16(r1);
                    l[q] = __float2bfloat16(r1 - __bfloat162float(m[q]));
                }
                __nv_bfloat162 P;
                P.x = h[0]; P.y = h[1];
                *(__nv_bfloat162*)(p.so + gr * p.ldso + gc) = P;
                P.x = h[2]; P.y = h[3];
                *(__nv_bfloat162*)(p.so + (gr + 8) * p.ldso + gc) = P;
                P.x = m[0]; P.y = m[1];
                *(__nv_bfloat162*)(p.so + p.sso + gr * p.ldso + gc) = P;
                P.x = m[2]; P.y = m[3];
                *(__nv_bfloat162*)(p.so + p.sso + (gr + 8) * p.ldso + gc) = P;
                P.x = l[0]; P.y = l[1];
                *(__nv_bfloat162*)(p.so + 2 * p.sso + gr * p.ldso + gc) = P;
                P.x = l[2]; P.y = l[3];
                *(__nv_bfloat162*)(p.so + 2 * p.sso + (gr + 8) * p.ldso + gc) = P;
            }
        }
    }
}

// ---------------------------------------------------------------------------
// Split-K reduce: e = 0.5*ref - 0.5*sum_z P[z]; write float + bf16x3 splits
// ---------------------------------------------------------------------------
__global__ void reduce_k(const float* __restrict__ P, int nsplit,
                         const float* __restrict__ ref, int ldref,
                         float* __restrict__ out, int outoff, int N,
                         bf16* __restrict__ so, long sso) {
    const int idx = blockIdx.x * blockDim.x + threadIdx.x;
    if (idx >= 512 * N) return;
    const int  b    = idx / N;
    const int  f    = idx - b * N;
    const long slab = (long)512 * N;
    float s = 0.0f;
    for (int z = 0; z < nsplit; ++z) s += P[z * slab + idx];
    const float e = 0.5f * ref[(long)b * ldref + f] - 0.5f * s;
    out[(long)b * OUT_LD + outoff + f] = e;
    const bf16 h = __float2bfloat16(e);
    const float r1 = e - __bfloat162float(h);
    const bf16 m = __float2bfloat16(r1);
    so[idx]           = h;
    so[sso + idx]     = m;
    so[2 * sso + idx] = __float2bfloat16(r1 - __bfloat162float(m));
}

// ---------------------------------------------------------------------------
// splitters (weights / inputs, once per launch)
// ---------------------------------------------------------------------------
__global__ void split_k(const float* __restrict__ in, int ld, int rows, int cols,
                        bf16* __restrict__ out) {
    const long n = (long)rows * cols;
    const long idx = (long)blockIdx.x * blockDim.x + threadIdx.x;
    if (idx >= n) return;
    const int r = (int)(idx / cols), c = (int)(idx - (long)r * cols);
    const float a = in[(long)r * ld + c];
    const bf16 h = __float2bfloat16(a);
    const float f1 = a - __bfloat162float(h);
    const bf16 m = __float2bfloat16(f1);
    out[idx]         = h;
    out[n + idx]     = m;
    out[2 * n + idx] = __float2bfloat16(f1 - __bfloat162float(m));
}
__global__ void splitT_k(const float* __restrict__ in, int ldin, int K, int N,
                         bf16* __restrict__ out) {
    const long n = (long)N * K;
    const long idx = (long)blockIdx.x * blockDim.x + threadIdx.x;
    if (idx >= n) return;
    const int nn = (int)(idx / K), k = (int)(idx - (long)nn * K);
    const float a = in[(long)k * ldin + nn];
    const bf16 h = __float2bfloat16(a);
    const float f1 = a - __bfloat162float(h);
    const bf16 m = __float2bfloat16(f1);
    out[idx]         = h;
    out[n + idx]     = m;
    out[2 * n + idx] = __float2bfloat16(f1 - __bfloat162float(m));
}

// ---------------------------------------------------------------------------
// LIF update; emits ed1/eg3 (float) and x1..3 bf16x3 splits
// ---------------------------------------------------------------------------
__global__ void lif_k(float* dout) {
    const long idx = (long)blockIdx.x * blockDim.x + threadIdx.x;
    if (idx >= 3L * S_LAYER) return;
    const int L = (int)(idx / S_LAYER);
    const int r = (int)(idx - (long)L * S_LAYER);

    const float tin = g_tin[idx];
    float j = g_state[idx];
    float v = g_state[3L * S_LAYER + idx];
    float x = g_state[6L * S_LAYER + idx];

    j = j + 0.25f * (tin - j);
    v = v + 0.05f * (j - v);
    const float spk = (v > 1.0f) ? 1.0f : 0.0f;
    v = v * (1.0f - spk);
    x = x * (1.0f - 0.025f) + spk;

    g_state[idx] = j;
    g_state[3L * S_LAYER + idx] = v;
    g_state[6L * S_LAYER + idx] = x;

    // x splits for phase-B GEMMs (slab [3][512][4096] per layer)
    const long xb = AOFF_X1 + (long)L * 6291456L + r;
    const bf16 h = __float2bfloat16(x);
    const float f1 = x - __bfloat162float(h);
    const bf16 m = __float2bfloat16(f1);
    g_act[xb]            = h;
    g_act[xb + 2097152L] = m;
    g_act[xb + 4194304L] = __float2bfloat16(f1 - __bfloat162float(m));

    if (L == 0) {                         // ed1 = 0.5*x1 - c1h
        const int b = r >> 12, f = r & 4095;
        dout[(long)b * OUT_LD + 13312 + f] = 0.5f * x - g_c1h[r];
    } else if (L == 2) {                  // eg3 = 0.5*x3 - c2h
        const int b = r >> 12, f = r & 4095;
        dout[(long)b * OUT_LD + 9216 + f] = 0.5f * x - g_c2h[r];
    }
}

__global__ void zero_k(float* dout) {
    const long n1 = 9L * S_LAYER;
    const long n2 = 27525120L;            // act EG0..ED4 region
    const long n3 = 512L * OUT_LD;
    for (long i = (long)blockIdx.x * blockDim.x + threadIdx.x; i < n1 + n2 + n3;
         i += (long)gridDim.x * blockDim.x) {
        if (i < n1)            g_state[i] = 0.0f;
        else if (i < n1 + n2)  g_act[i - n1] = __float2bfloat16(0.0f);
        else                   dout[i - n1 - n2] = 0.0f;
    }
}

// ---------------------------------------------------------------------------
static void tgemm(const bf16* A1, long sA1, int lda1,
                  const bf16* B1, long sB1, int ldb1, int K1,
                  const bf16* A2, long sA2, int lda2,
                  const bf16* B2, long sB2, int ldb2, int K2,
                  float* C, int ldc,
                  const float* a0, int l0, float g0,
                  const float* a1, int l1, float g1,
                  float alpha, int N,
                  bf16* so = nullptr, long sso = 0, int ldso = 0,
                  int kc = 0, int nsplit = 1, long czstride = 0) {
    TG p;
    p.A1 = A1; p.sA1 = sA1; p.lda1 = lda1;
    p.B1 = B1; p.sB1 = sB1; p.ldb1 = ldb1; p.K1 = K1;
    p.A2 = A2 ? A2 : A1; p.sA2 = sA2; p.lda2 = lda2;
    p.B2 = B2 ? B2 : B1; p.sB2 = sB2; p.ldb2 = ldb2; p.K2 = K2;
    p.C = C; p.ldc = ldc;
    p.aux0 = a0; p.ld0 = l0; p.g0 = g0;
    p.aux1 = a1; p.ld1 = l1; p.g1 = g1;
    p.alpha = alpha;
    p.so = so; p.sso = sso; p.ldso = ldso;
    p.kc = kc; p.czstride = czstride;
    dim3 grid(N / 128, 4, nsplit);
    gemm_mma<<<grid, 256, SMEM_MM>>>(p);
}

extern "C" void kernel_launch(void* const* d_in, const int* in_sizes, int n_in,
                              void* d_out, int out_size) {
    (void)in_sizes; (void)n_in; (void)out_size;
    const float* xd = (const float*)d_in[0];   // (512, 1024)
    const float* yt = (const float*)d_in[1];   // (512, 512)
    const float* W0 = (const float*)d_in[2];
    const float* V0 = (const float*)d_in[3];
    const float* W1 = (const float*)d_in[4];
    const float* V1 = (const float*)d_in[5];
    const float* W2 = (const float*)d_in[6];
    const float* V2 = (const float*)d_in[7];
    const float* W3 = (const float*)d_in[8];
    const float* V3 = (const float*)d_in[9];
    float* out = (float*)d_out;

    cudaFuncSetAttribute(gemm_mma, cudaFuncAttributeMaxDynamicSharedMemorySize, SMEM_MM);

    float *st, *tin, *c1h, *c2h, *pA, *pB; bf16 *w, *act, *io;
    cudaGetSymbolAddress((void**)&st,  g_state);
    cudaGetSymbolAddress((void**)&tin, g_tin);
    cudaGetSymbolAddress((void**)&c1h, g_c1h);
    cudaGetSymbolAddress((void**)&c2h, g_c2h);
    cudaGetSymbolAddress((void**)&w,   g_w);
    cudaGetSymbolAddress((void**)&act, g_act);
    cudaGetSymbolAddress((void**)&io,  g_io);
    cudaGetSymbolAddress((void**)&pA,  g_pA);
    cudaGetSymbolAddress((void**)&pB,  g_pB);

    float* x1 = st + 6L * S_LAYER;
    float* x2 = st + 7L * S_LAYER;
    float* x3 = st + 8L * S_LAYER;
    float* t1 = tin;
    float* t2 = tin + S_LAYER;
    float* t3 = tin + 2L * S_LAYER;

    float* eg1 = out + 1024;
    float* eg2 = out + 5120;
    float* eg3 = out + 9216;     // written by lif_k
    float* ed1 = out + 13312;    // written by lif_k
    float* ed2 = out + 17408;
    float* ed3 = out + 21504;

    zero_k<<<2048, 256>>>(out);

    // ---- weight / input splits (once per launch) ----
    split_k<<<(1024 * 4096 + 255) / 256, 256>>>(W0, 4096, 1024, 4096, w + OFF_W0d);
    split_k<<<(4096 * 1024 + 255) / 256, 256>>>(V0, 1024, 4096, 1024, w + OFF_V0d);
    split_k<<<(4096 * 4096 + 255) / 256, 256>>>(W1, 4096, 4096, 4096, w + OFF_W1d);
    split_k<<<(4096 * 4096 + 255) / 256, 256>>>(V1, 4096, 4096, 4096, w + OFF_V1d);
    split_k<<<(4096 * 4096 + 255) / 256, 256>>>(W2, 4096, 4096, 4096, w + OFF_W2d);
    split_k<<<(4096 * 4096 + 255) / 256, 256>>>(V2, 4096, 4096, 4096, w + OFF_V2d);
    split_k<<<(4096 * 512  + 255) / 256, 256>>>(W3, 512,  4096, 512,  w + OFF_W3d);
    split_k<<<(512  * 4096 + 255) / 256, 256>>>(V3, 4096, 512,  4096, w + OFF_V3d);
    splitT_k<<<(4096 * 1024 + 255) / 256, 256>>>(W0, 4096, 1024, 4096, w + OFF_Wt0);
    splitT_k<<<(4096 * 4096 + 255) / 256, 256>>>(W1, 4096, 4096, 4096, w + OFF_Wt1);
    splitT_k<<<(4096 * 4096 + 255) / 256, 256>>>(V1, 4096, 4096, 4096, w + OFF_Vt1);
    splitT_k<<<(4096 * 4096 + 255) / 256, 256>>>(W2, 4096, 4096, 4096, w + OFF_Wt2);
    splitT_k<<<(4096 * 4096 + 255) / 256, 256>>>(V2, 4096, 4096, 4096, w + OFF_Vt2);
    splitT_k<<<(4096 * 512  + 255) / 256, 256>>>(V3, 4096, 512,  4096, w + OFF_Vt3);
    split_k<<<(512 * 1024 + 255) / 256, 256>>>(xd, 1024, 512, 1024, io);
    split_k<<<(512 * 512  + 255) / 256, 256>>>(yt, 512,  512, 512,  io + 1572864);

    // ---- step-invariant terms ----
    // c1h = 0.5 * xd @ V0^T   (N=4096, K=1024)
    tgemm(io, 524288, 1024, w + OFF_V0d, 4194304, 1024, 1024,
          nullptr, 0, 0, nullptr, 0, 0, 0,
          c1h, 4096, nullptr, 0, 0.f, nullptr, 0, 0.f, 0.5f, 4096);
    // c2h = 0.5 * yt @ W3^T   (N=4096, K=512)
    tgemm(io + 1572864, 262144, 512, w + OFF_W3d, 2097152, 512, 512,
          nullptr, 0, 0, nullptr, 0, 0, 0,
          c2h, 4096, nullptr, 0, 0.f, nullptr, 0, 0.f, 0.5f, 4096);

    const int NUM_STEPS = 25;
    for (int t = 0; t < NUM_STEPS; t++) {
        // ---- Phase A: injected currents (2-segment K, bf16x3 slabs) ----
        // t1 = eg0@W0 + ed2@V1 - ed1 - eg1
        tgemm(act + AOFF_EG0, 524288, 1024, w + OFF_Wt0, 4194304, 1024, 1024,
              act + AOFF_ED2, 2097152, 4096, w + OFF_Vt1, 16777216, 4096, 4096,
              t1, 4096, ed1, OUT_LD, -1.f, eg1, OUT_LD, -1.f, 1.f, 4096);
        // t2 = eg1@W1 + ed3@V2 - ed2 - eg2
        tgemm(act + AOFF_EG1, 2097152, 4096, w + OFF_Wt1, 16777216, 4096, 4096,
              act + AOFF_ED3, 2097152, 4096, w + OFF_Vt2, 16777216, 4096, 4096,
              t2, 4096, ed2, OUT_LD, -1.f, eg2, OUT_LD, -1.f, 1.f, 4096);
        // t3 = eg2@W2 + ed4@V3 - ed3 - eg3
        tgemm(act + AOFF_EG2, 2097152, 4096, w + OFF_Wt2, 16777216, 4096, 4096,
              act + AOFF_ED4, 262144, 512,  w + OFF_Vt3, 2097152, 512, 512,
              t3, 4096, ed3, OUT_LD, -1.f, eg3, OUT_LD, -1.f, 1.f, 4096);

        // ---- LIF update (+ ed1, eg3, x splits) ----
        lif_k<<<(3 * S_LAYER + 255) / 256, 256>>>(out);

        // ---- Phase B: error signals (fused split emission) ----
        // eg1 = 0.5*x1 - 0.5*(x2 @ W1^T)
        tgemm(act + AOFF_X2, 2097152, 4096, w + OFF_W1d, 16777216, 4096, 4096,
              nullptr, 0, 0, nullptr, 0, 0, 0,
              eg1, OUT_LD, x1, 4096, 0.5f, nullptr, 0, 0.f, -0.5f, 4096,
              act + AOFF_EG1, 2097152, 4096);
        // ed2 = 0.5*x2 - 0.5*(x1 @ V1^T)
        tgemm(act + AOFF_X1, 2097152, 4096, w + OFF_V1d, 16777216, 4096, 4096,
              nullptr, 0, 0, nullptr, 0, 0, 0,
              ed2, OUT_LD, x2, 4096, 0.5f, nullptr, 0, 0.f, -0.5f, 4096,
              act + AOFF_ED2, 2097152, 4096);
        // eg2 = 0.5*x2 - 0.5*(x3 @ W2^T)
        tgemm(act + AOFF_X3, 2097152, 4096, w + OFF_W2d, 16777216, 4096, 4096,
              nullptr, 0, 0, nullptr, 0, 0, 0,
              eg2, OUT_LD, x2, 4096, 0.5f, nullptr, 0, 0.f, -0.5f, 4096,
              act + AOFF_EG2, 2097152, 4096);
        // ed3 = 0.5*x3 - 0.5*(x2 @ V2^T)
        tgemm(act + AOFF_X2, 2097152, 4096, w + OFF_V2d, 16777216, 4096, 4096,
              nullptr, 0, 0, nullptr, 0, 0, 0,
              ed3, OUT_LD, x3, 4096, 0.5f, nullptr, 0, 0.f, -0.5f, 4096,
              act + AOFF_ED3, 2097152, 4096);

        // eg0: split-K 4x of x1 @ W0^T (N=1024, K=4096) -> partials + reduce
        tgemm(act + AOFF_X1, 2097152, 4096, w + OFF_W0d, 4194304, 4096, 4096,
              nullptr, 0, 0, nullptr, 0, 0, 0,
              pA, 1024, nullptr, 0, 0.f, nullptr, 0, 0.f, 1.f, 1024,
              nullptr, 0, 0, /*kc=*/1024, /*nsplit=*/4, /*czstride=*/524288);
        reduce_k<<<(512 * 1024 + 255) / 256, 256>>>(pA, 4, xd, 1024, out, 0, 1024,
                                                    act + AOFF_EG0, 524288);

        // ed4: split-K 8x of x3 @ V3^T (N=512, K=4096) -> partials + reduce
        tgemm(act + AOFF_X3, 2097152, 4096, w + OFF_V3d, 2097152, 4096, 4096,
              nullptr, 0, 0, nullptr, 0, 0, 0,
              pB, 512, nullptr, 0, 0.f, nullptr, 0, 0.f, 1.f, 512,
              nullptr, 0, 0, /*kc=*/512, /*nsplit=*/8, /*czstride=*/262144);
        reduce_k<<<(512 * 512 + 255) / 256, 256>>>(pB, 8, yt, 512, out, 25600, 512,
                                                   act + AOFF_ED4, 262144);
    }
}